// round 4
// baseline (speedup 1.0000x reference)
#include <cuda_runtime.h>
#include <math.h>
#include <stdint.h>

// Problem constants (fixed by setup_inputs)
#define B_   64
#define L_   680
#define C_   1024
#define NSEG 10

static const int       h_len[NSEG]   = {1,4,9,16,25,36,64,100,169,256};

__constant__ int       c_start[NSEG] = {0,1,5,14,30,55,91,155,255,424};
__constant__ int       c_len[NSEG]   = {1,4,9,16,25,36,64,100,169,256};
__constant__ long long c_base[NSEG]  = {0LL,8192LL,73728LL,294912LL,819200LL,
                                        1843200LL,3612672LL,7282688LL,13836288LL,26296320LL};
// tile prefix tables (fixed geometry): mtiles = ceil(64*len/128)
//   scores: tiles_i = mtiles_i * (i+1); attnV: tiles_i = mtiles_i * 8
__constant__ int c_stp[NSEG + 1] = {0,1,5,20,52,117,225,449,849,1614,2894};
__constant__ int c_atp[NSEG + 1] = {0,8,24,64,128,232,376,632,1032,1712,2736};

// Static device scratch
__device__ float g_Q  [44564480];   // 43520 x 1024
__device__ float g_K  [1310720];    // 1280 x 1024
__device__ float g_V  [1310720];    // 1280 x 1024
__device__ float g_S  [47267840];   // segment-packed scores/attn
__device__ float g_MC [44564480];   // mem_combined, 43520 x 1024
__device__ float g_mid[5570560];    // 43520 x 128 (mid_k | mid_v)
__device__ float g_w12[131072];     // 1024 x 128 (wk1 | wv1)
__device__ float g_b12[128];        // bk1 | bv1

__device__ __forceinline__ float f2tf32(float x) {
    uint32_t r;
    asm("cvt.rna.tf32.f32 %0, %1;" : "=r"(r) : "f"(x));
    float out;
    asm("mov.b32 %0, %1;" : "=f"(out) : "r"(r));
    return out;
}

// ---------------------------------------------------------------------------
// GEMM core: C[m0:,n0:] tile (128x128), K-loop over full K.
//   A: [M,K] row-major (lda); alen>0 => row remap (m/alen)*680+astart+(m%alen)
//   B: NN = [K,N], NT = [N,K]
//   C: [M,N]; clen>0 => row remap
// A (and B in NT) staged in smem as [row][16] with k-packed swizzle:
//   col(k,row) = 4*((k&3) ^ ((row>>1)&3)) + (k>>2)
// so one LDS.128 per fragment row yields k = {t4, t4+4, t4+8, t4+12}.
// Values tf32-converted at store; fragment reads are raw bit loads.
// 8 warps, warp tile 64x32 (wm=(w&1)*64, wn=(w>>1)*32), m16n8k8 tf32 mma.
// ---------------------------------------------------------------------------
template<int TRANSB>
__device__ __forceinline__ void gemm_core(
    const float* __restrict__ A, int lda,
    const float* __restrict__ B, int ldb,
    float* __restrict__ C, int ldc,
    int M, int N, int K,
    int alen, int astart, int clen, int cstart,
    const float* __restrict__ bias,
    const float* __restrict__ gate_logit,
    int m0, int n0)
{
    __shared__ float As[2][128][16];
    constexpr int BR = TRANSB ? 128 : 16;
    constexpr int BC = TRANSB ? 16  : 136;
    __shared__ float Bs[2][BR][BC];

    const int tid  = threadIdx.x;
    const int lane = tid & 31;
    const int w    = tid >> 5;
    const int wm   = (w & 1) * 64;
    const int wn   = (w >> 1) * 32;
    const int g    = lane >> 2;
    const int t4   = lane & 3;

    float acc[4][4][4];
    #pragma unroll
    for (int i = 0; i < 4; i++)
        #pragma unroll
        for (int j = 0; j < 4; j++)
            #pragma unroll
            for (int k = 0; k < 4; k++) acc[i][j][k] = 0.f;

    // ---- A global-load setup ----
    const int a_m  = tid >> 1;
    const int a_kh = (tid & 1) * 8;
    const int am   = m0 + a_m;
    const bool amOK = am < M;
    long long arow = (alen > 0)
        ? (long long)(am / alen) * L_ + astart + (am % alen)
        : (long long)am;
    const float* Aptr = A + arow * (long long)lda + a_kh;
    const int a_swz = (a_m >> 1) & 3;
    const int a_in0 = a_kh >> 2;          // 0 or 2

    // ---- B global-load setup ----
    const float* Bptr;
    bool bOK;
    int b_r, b_c, b_swz = 0, b_in0 = 0;
    if (!TRANSB) {
        int kr = tid >> 4;                // 0..15
        int cn = (tid & 15) * 8;          // 0..120
        bOK  = (n0 + cn) < N;
        Bptr = B + (long long)kr * ldb + n0 + cn;
        b_r = kr; b_c = cn;
    } else {
        int bn = tid >> 1;                // 0..127
        int kh = (tid & 1) * 8;
        bOK  = (n0 + bn) < N;
        Bptr = B + (long long)(n0 + bn) * ldb + kh;
        b_r = bn; b_c = kh;
        b_swz = (bn >> 1) & 3;
        b_in0 = kh >> 2;
    }

    float4 ra0, ra1, rb0, rb1;
    const float4 z4 = make_float4(0.f, 0.f, 0.f, 0.f);

    auto ldg = [&](int k0) {
        if (amOK) {
            ra0 = *(const float4*)(Aptr + k0);
            ra1 = *(const float4*)(Aptr + k0 + 4);
        } else { ra0 = z4; ra1 = z4; }
        if (!TRANSB) {
            const float* p = Bptr + (long long)k0 * ldb;
            if (bOK) { rb0 = *(const float4*)p; rb1 = *(const float4*)(p + 4); }
            else     { rb0 = z4; rb1 = z4; }
        } else {
            if (bOK) { rb0 = *(const float4*)(Bptr + k0); rb1 = *(const float4*)(Bptr + k0 + 4); }
            else     { rb0 = z4; rb1 = z4; }
        }
    };

    auto sts = [&](int buf) {
        {
            float v[8] = {ra0.x, ra0.y, ra0.z, ra0.w, ra1.x, ra1.y, ra1.z, ra1.w};
            #pragma unroll
            for (int j = 0; j < 8; j++) {
                int col = 4 * ((j & 3) ^ a_swz) + a_in0 + (j >> 2);
                As[buf][a_m][col] = f2tf32(v[j]);
            }
        }
        if (!TRANSB) {
            float4 c0 = make_float4(f2tf32(rb0.x), f2tf32(rb0.y), f2tf32(rb0.z), f2tf32(rb0.w));
            float4 c1 = make_float4(f2tf32(rb1.x), f2tf32(rb1.y), f2tf32(rb1.z), f2tf32(rb1.w));
            *(float4*)&Bs[buf][b_r][b_c]     = c0;
            *(float4*)&Bs[buf][b_r][b_c + 4] = c1;
        } else {
            float v[8] = {rb0.x, rb0.y, rb0.z, rb0.w, rb1.x, rb1.y, rb1.z, rb1.w};
            #pragma unroll
            for (int j = 0; j < 8; j++) {
                int col = 4 * ((j & 3) ^ b_swz) + b_in0 + (j >> 2);
                Bs[buf][b_r][col] = f2tf32(v[j]);
            }
        }
    };

    auto compute = [&](int buf) {
        // ---- B fragments: 4 ni x {kb0:b0,b1, kb8:b0,b1} ----
        uint32_t bfr[4][4];
        #pragma unroll
        for (int ni = 0; ni < 4; ni++) {
            if (TRANSB) {
                int row = wn + ni * 8 + g;
                const float4 v = *(const float4*)&Bs[buf][row][4 * (t4 ^ ((row >> 1) & 3))];
                bfr[ni][0] = __float_as_uint(v.x);
                bfr[ni][1] = __float_as_uint(v.y);
                bfr[ni][2] = __float_as_uint(v.z);
                bfr[ni][3] = __float_as_uint(v.w);
            } else {
                int nb = wn + ni * 8 + g;
                bfr[ni][0] = __float_as_uint(Bs[buf][t4     ][nb]);
                bfr[ni][1] = __float_as_uint(Bs[buf][t4 + 4 ][nb]);
                bfr[ni][2] = __float_as_uint(Bs[buf][t4 + 8 ][nb]);
                bfr[ni][3] = __float_as_uint(Bs[buf][t4 + 12][nb]);
            }
        }
        #pragma unroll
        for (int mi = 0; mi < 4; mi++) {
            int rlo = wm + mi * 16 + g;
            int rhi = rlo + 8;
            const float4 lo = *(const float4*)&As[buf][rlo][4 * (t4 ^ ((rlo >> 1) & 3))];
            const float4 hi = *(const float4*)&As[buf][rhi][4 * (t4 ^ ((rhi >> 1) & 3))];
            uint32_t a0[4] = {__float_as_uint(lo.x), __float_as_uint(hi.x),
                              __float_as_uint(lo.y), __float_as_uint(hi.y)};
            uint32_t a1[4] = {__float_as_uint(lo.z), __float_as_uint(hi.z),
                              __float_as_uint(lo.w), __float_as_uint(hi.w)};
            #pragma unroll
            for (int ni = 0; ni < 4; ni++) {
                asm volatile(
                    "mma.sync.aligned.m16n8k8.row.col.f32.tf32.tf32.f32 "
                    "{%0,%1,%2,%3},{%4,%5,%6,%7},{%8,%9},{%0,%1,%2,%3};"
                    : "+f"(acc[mi][ni][0]), "+f"(acc[mi][ni][1]),
                      "+f"(acc[mi][ni][2]), "+f"(acc[mi][ni][3])
                    : "r"(a0[0]), "r"(a0[1]), "r"(a0[2]), "r"(a0[3]),
                      "r"(bfr[ni][0]), "r"(bfr[ni][1]));
            }
            #pragma unroll
            for (int ni = 0; ni < 4; ni++) {
                asm volatile(
                    "mma.sync.aligned.m16n8k8.row.col.f32.tf32.tf32.f32 "
                    "{%0,%1,%2,%3},{%4,%5,%6,%7},{%8,%9},{%0,%1,%2,%3};"
                    : "+f"(acc[mi][ni][0]), "+f"(acc[mi][ni][1]),
                      "+f"(acc[mi][ni][2]), "+f"(acc[mi][ni][3])
                    : "r"(a1[0]), "r"(a1[1]), "r"(a1[2]), "r"(a1[3]),
                      "r"(bfr[ni][2]), "r"(bfr[ni][3]));
            }
        }
    };

    // ---- pipelined main loop ----
    ldg(0);
    sts(0);
    __syncthreads();
    int cur = 0;
    for (int k0 = 16;; k0 += 16) {
        bool more = k0 < K;
        if (more) ldg(k0);
        compute(cur);
        if (!more) break;
        sts(cur ^ 1);
        __syncthreads();
        cur ^= 1;
    }

    // ---- epilogue ----
    float gate = 1.0f;
    if (gate_logit) gate = 1.0f / (1.0f + expf(-(*gate_logit)));

    #pragma unroll
    for (int mi = 0; mi < 4; mi++) {
        #pragma unroll
        for (int rr = 0; rr < 2; rr++) {
            int m = m0 + wm + mi * 16 + g + rr * 8;
            if (m >= M) continue;
            long long crow = (clen > 0)
                ? (long long)(m / clen) * L_ + cstart + (m % clen)
                : (long long)m;
            float* cp = C + crow * (long long)ldc;
            #pragma unroll
            for (int ni = 0; ni < 4; ni++) {
                int n = n0 + wn + ni * 8 + t4 * 2;
                if (n >= N) continue;
                float v0 = acc[mi][ni][rr * 2 + 0];
                float v1 = acc[mi][ni][rr * 2 + 1];
                if (bias) { v0 += bias[n]; v1 += bias[n + 1]; }
                cp[n]     = v0 * gate;
                cp[n + 1] = v1 * gate;
            }
        }
    }
}

// ---------------------------------------------------------------------------
// Plain (dense) GEMM wrappers
// ---------------------------------------------------------------------------
__global__ __launch_bounds__(256)
void tgemm_nn(const float* __restrict__ A, int lda,
              const float* __restrict__ B, int ldb,
              float* __restrict__ C, int ldc,
              int M, int N, int K,
              const float* __restrict__ bias,
              const float* __restrict__ gate_logit)
{
    gemm_core<0>(A, lda, B, ldb, C, ldc, M, N, K, 0, 0, 0, 0,
                 bias, gate_logit, blockIdx.y * 128, blockIdx.x * 128);
}

// Fused scores kernel: all 10 segments in one launch (2894 tiles)
__global__ __launch_bounds__(256)
void scores_kernel()
{
    int t = blockIdx.x;
    int seg = 0;
    #pragma unroll
    for (int i = 1; i < NSEG; i++) if (t >= c_stp[i]) seg = i;
    int local = t - c_stp[seg];
    int nt = seg + 1;
    int tm = local / nt;
    int tn = local - tm * nt;
    int len = c_len[seg], start = c_start[seg];
    int Nseg = 128 * nt, Mseg = 64 * len;
    gemm_core<1>(g_Q, C_, g_K, C_, g_S + c_base[seg], Nseg,
                 Mseg, Nseg, C_, len, start, 0, 0, nullptr, nullptr,
                 tm * 128, tn * 128);
}

// Fused attn@V kernel: all 10 segments in one launch (2736 tiles)
__global__ __launch_bounds__(256)
void attnv_kernel()
{
    int t = blockIdx.x;
    int seg = 0;
    #pragma unroll
    for (int i = 1; i < NSEG; i++) if (t >= c_atp[i]) seg = i;
    int local = t - c_atp[seg];
    int tm = local >> 3;
    int tn = local & 7;
    int len = c_len[seg], start = c_start[seg];
    int Nseg = 128 * (seg + 1), Mseg = 64 * len;
    gemm_core<0>(g_S + c_base[seg], Nseg, g_V, C_, g_MC, C_,
                 Mseg, C_, Nseg, 0, 0, len, start, nullptr, nullptr,
                 tm * 128, tn * 128);
}

// ---------------------------------------------------------------------------
// Row softmax over segment-packed g_S; scale = (1/32)/clip(exp(log_temp))
// ---------------------------------------------------------------------------
__global__ void softmax_kernel(const float* __restrict__ log_temp)
{
    int row = blockIdx.x;           // b*L + l
    int b = row / L_;
    int l = row - b * L_;

    int seg = 0;
    #pragma unroll
    for (int s2 = 1; s2 < NSEG; s2++)
        if (l >= c_start[s2]) seg = s2;

    const int n   = 128 * (seg + 1);
    const int len = c_len[seg];
    float* p = g_S + c_base[seg] + ((long long)b * len + (l - c_start[seg])) * (long long)n;

    float t = expf(*log_temp);
    t = fminf(fmaxf(t, 0.05f), 1.0f);
    const float scale = (1.0f / 32.0f) / t;

    __shared__ float sh[8];
    const int lane = threadIdx.x & 31;
    const int w    = threadIdx.x >> 5;

    float m = -1e30f;
    for (int j = threadIdx.x; j < n; j += 256) m = fmaxf(m, p[j] * scale);
    #pragma unroll
    for (int o = 16; o; o >>= 1) m = fmaxf(m, __shfl_xor_sync(0xffffffffu, m, o));
    if (lane == 0) sh[w] = m;
    __syncthreads();
    m = sh[lane & 7];
    #pragma unroll
    for (int o = 4; o; o >>= 1) m = fmaxf(m, __shfl_xor_sync(0xffffffffu, m, o));

    float sum = 0.f;
    for (int j = threadIdx.x; j < n; j += 256) {
        float e = expf(p[j] * scale - m);
        p[j] = e;
        sum += e;
    }
    #pragma unroll
    for (int o = 16; o; o >>= 1) sum += __shfl_xor_sync(0xffffffffu, sum, o);
    __syncthreads();
    if (lane == 0) sh[w] = sum;
    __syncthreads();
    sum = sh[lane & 7];
    #pragma unroll
    for (int o = 4; o; o >>= 1) sum += __shfl_xor_sync(0xffffffffu, sum, o);

    const float inv = 1.0f / sum;
    for (int j = threadIdx.x; j < n; j += 256) p[j] *= inv;
}

// Pack wk1|wv1 -> g_w12 [1024x128], bk1|bv1 -> g_b12 [128]
__global__ void pack_w12_kernel(const float* __restrict__ wk1,
                                const float* __restrict__ wv1,
                                const float* __restrict__ bk1,
                                const float* __restrict__ bv1)
{
    int idx = blockIdx.x * 256 + threadIdx.x;
    if (idx < 1024 * 64) {
        int k = idx >> 6, j = idx & 63;
        g_w12[k * 128 + j]      = wk1[idx];
        g_w12[k * 128 + 64 + j] = wv1[idx];
    }
    if (idx < 64) {
        g_b12[idx]      = bk1[idx];
        g_b12[64 + idx] = bv1[idx];
    }
}

__global__ void tail_kernel(float* out, long long off)
{
    if (threadIdx.x < 2) out[off + threadIdx.x] = 0.f;
}

// ---------------------------------------------------------------------------
extern "C" void kernel_launch(void* const* d_in, const int* in_sizes, int n_in,
                              void* d_out, int out_size)
{
    const float* x   = (const float*)d_in[0];
    const float* mem = (const float*)d_in[1];
    const float* Wq  = (const float*)d_in[2];
    const float* Wk  = (const float*)d_in[3];
    const float* Wv  = (const float*)d_in[4];
    const float* wk1 = (const float*)d_in[5];
    const float* bk1 = (const float*)d_in[6];
    const float* wk2 = (const float*)d_in[7];
    const float* bk2 = (const float*)d_in[8];
    const float* wv1 = (const float*)d_in[9];
    const float* bv1 = (const float*)d_in[10];
    const float* wv2 = (const float*)d_in[11];
    const float* bv2 = (const float*)d_in[12];
    const float* gk  = (const float*)d_in[13];
    const float* gv  = (const float*)d_in[14];
    const float* lt  = (const float*)d_in[15];
    float* out = (float*)d_out;

    float *Q, *Kp, *Vp, *mid, *w12, *b12;
    cudaGetSymbolAddress((void**)&Q,   g_Q);
    cudaGetSymbolAddress((void**)&Kp,  g_K);
    cudaGetSymbolAddress((void**)&Vp,  g_V);
    cudaGetSymbolAddress((void**)&mid, g_mid);
    cudaGetSymbolAddress((void**)&w12, g_w12);
    cudaGetSymbolAddress((void**)&b12, g_b12);

    // 0) pack bottleneck down-proj weights
    pack_w12_kernel<<<256, 256>>>(wk1, wv1, bk1, bv1);

    // 1) projections
    tgemm_nn<<<dim3(C_ / 128, (B_ * L_) / 128), 256>>>(x,   C_, Wq, C_, Q,  C_, B_ * L_,    C_, C_, nullptr, nullptr);
    tgemm_nn<<<dim3(C_ / 128, 10), 256>>>(mem, C_, Wk, C_, Kp, C_, NSEG * 128, C_, C_, nullptr, nullptr);
    tgemm_nn<<<dim3(C_ / 128, 10), 256>>>(mem, C_, Wv, C_, Vp, C_, NSEG * 128, C_, C_, nullptr, nullptr);

    // 2) all score GEMMs, one launch
    scores_kernel<<<2894, 256>>>();

    // 3) softmax in-place
    softmax_kernel<<<B_ * L_, 256>>>(lt);

    // 4) all attn @ V GEMMs, one launch
    attnv_kernel<<<2736, 256>>>();

    // 5) fused mid GEMM: mid = MC @ [wk1|wv1] + [bk1|bv1]
    {
        float* MC;
        cudaGetSymbolAddress((void**)&MC, g_MC);
        tgemm_nn<<<dim3(1, (B_ * L_) / 128), 256>>>(MC, C_, w12, 128, mid, 128,
                                                    B_ * L_, 128, C_, b12, nullptr);
    }

    // 6) up-projections with gate epilogue
    tgemm_nn<<<dim3(C_ / 128, (B_ * L_) / 128), 256>>>(mid,      128, wk2, C_, out, C_,
                                                       B_ * L_, C_, 64, bk2, gk);
    tgemm_nn<<<dim3(C_ / 128, (B_ * L_) / 128), 256>>>(mid + 64, 128, wv2, C_,
                                                       out + (long long)B_ * L_ * C_, C_,
                                                       B_ * L_, C_, 64, bv2, gv);

    // 7) trailing two scalar zeros
    tail_kernel<<<1, 32>>>(out, 2LL * B_ * L_ * C_);
}

// round 5
// speedup vs baseline: 1.0267x; 1.0267x over previous
#include <cuda_runtime.h>
#include <math.h>
#include <stdint.h>

// Problem constants (fixed by setup_inputs)
#define B_   64
#define L_   680
#define C_   1024
#define NSEG 10

__constant__ int       c_start[NSEG] = {0,1,5,14,30,55,91,155,255,424};
__constant__ int       c_len[NSEG]   = {1,4,9,16,25,36,64,100,169,256};
__constant__ long long c_base[NSEG]  = {0LL,8192LL,73728LL,294912LL,819200LL,
                                        1843200LL,3612672LL,7282688LL,13836288LL,26296320LL};
// tile prefix tables (fixed geometry): mtiles_i = ceil(64*len_i/128)
//   scores: tiles_i = mtiles_i * (i+1); attnV: tiles_i = mtiles_i * 8
__constant__ int c_stp[NSEG + 1] = {0,1,5,20,52,117,225,449,849,1614,2894};
__constant__ int c_atp[NSEG + 1] = {0,8,24,64,128,232,376,632,1032,1712,2736};

// Static device scratch
__device__ float g_Q  [44564480];   // 43520 x 1024
__device__ float g_K  [1310720];    // 1280 x 1024
__device__ float g_V  [1310720];    // 1280 x 1024
__device__ float g_S  [47267840];   // segment-packed scores/attn
__device__ float g_MC [44564480];   // mem_combined, 43520 x 1024
__device__ float g_mid[5570560];    // 43520 x 128 (mid_k | mid_v)
__device__ float g_w12[131072];     // 1024 x 128 (wk1 | wv1)
__device__ float g_b12[128];        // bk1 | bv1

__device__ __forceinline__ float f2tf32(float x) {
    uint32_t r;
    asm("cvt.rna.tf32.f32 %0, %1;" : "=r"(r) : "f"(x));
    float out;
    asm("mov.b32 %0, %1;" : "=f"(out) : "r"(r));
    return out;
}

// ---------------------------------------------------------------------------
// R3-proven GEMM core: one 128x128 C-tile at (m0, n0), K-loop over full K.
//   A: [M,K] row-major (lda); alen>0 => row remap (m/alen)*680+astart+(m%alen)
//   B: NN = [K,N] (ldb), NT = [N,K] (ldb)
//   C: [M,N] (ldc); clen>0 => row remap
// Double-buffered smem, As[k][m] / Bs[k][n], stride 136 (conflict-free).
// 8 warps, warp tile 64x32 (wm=(w&1)*64, wn=(w>>1)*32), m16n8k8 tf32 mma.
// ---------------------------------------------------------------------------
template<int TRANSB>
__device__ __forceinline__ void gemm_core(
    const float* __restrict__ A, int lda,
    const float* __restrict__ B, int ldb,
    float* __restrict__ C, int ldc,
    int M, int N, int K,
    int alen, int astart, int clen, int cstart,
    const float* __restrict__ bias,
    const float* __restrict__ gate_logit,
    int m0, int n0)
{
    __shared__ float As[2][16][136];
    __shared__ float Bs[2][16][136];

    const int tid  = threadIdx.x;
    const int lane = tid & 31;
    const int w    = tid >> 5;
    const int wm   = (w & 1) * 64;
    const int wn   = (w >> 1) * 32;
    const int g    = lane >> 2;     // 0..7
    const int t4   = lane & 3;      // 0..3

    float acc[4][4][4];
    #pragma unroll
    for (int i = 0; i < 4; i++)
        #pragma unroll
        for (int j = 0; j < 4; j++)
            #pragma unroll
            for (int k = 0; k < 4; k++) acc[i][j][k] = 0.f;

    // ---- A global-load setup: thread loads row m0+(tid>>1), 8 cols ----
    const int am   = m0 + (tid >> 1);
    const bool amOK = am < M;
    long long arow = (alen > 0)
        ? (long long)(am / alen) * L_ + astart + (am % alen)
        : (long long)am;
    const float* Aptr = A + arow * (long long)lda + (tid & 1) * 8;
    const int a_sm = tid >> 1;
    const int a_sk = (tid & 1) * 8;

    // ---- B global-load setup ----
    const float* Bptr;
    bool bOK;
    int b_sk, b_sn;
    if (!TRANSB) {
        int kr = tid >> 4;            // 0..15
        int cn = (tid & 15) * 8;      // 0..120
        bOK  = (n0 + cn) < N;
        Bptr = B + (long long)kr * ldb + n0 + cn;
        b_sk = kr; b_sn = cn;
    } else {
        int bn = tid >> 1;            // 0..127
        int ck = (tid & 1) * 8;
        bOK  = (n0 + bn) < N;
        Bptr = B + (long long)(n0 + bn) * ldb + ck;
        b_sk = ck; b_sn = bn;
    }

    float4 ra0, ra1, rb0, rb1;
    const float4 z4 = make_float4(0.f, 0.f, 0.f, 0.f);

    auto ldg = [&](int k0) {
        if (amOK) {
            ra0 = *(const float4*)(Aptr + k0);
            ra1 = *(const float4*)(Aptr + k0 + 4);
        } else { ra0 = z4; ra1 = z4; }
        if (!TRANSB) {
            const float* p = Bptr + (long long)k0 * ldb;
            if (bOK) { rb0 = *(const float4*)p; rb1 = *(const float4*)(p + 4); }
            else     { rb0 = z4; rb1 = z4; }
        } else {
            if (bOK) { rb0 = *(const float4*)(Bptr + k0); rb1 = *(const float4*)(Bptr + k0 + 4); }
            else     { rb0 = z4; rb1 = z4; }
        }
    };

    auto sts = [&](int buf) {
        As[buf][a_sk + 0][a_sm] = f2tf32(ra0.x);
        As[buf][a_sk + 1][a_sm] = f2tf32(ra0.y);
        As[buf][a_sk + 2][a_sm] = f2tf32(ra0.z);
        As[buf][a_sk + 3][a_sm] = f2tf32(ra0.w);
        As[buf][a_sk + 4][a_sm] = f2tf32(ra1.x);
        As[buf][a_sk + 5][a_sm] = f2tf32(ra1.y);
        As[buf][a_sk + 6][a_sm] = f2tf32(ra1.z);
        As[buf][a_sk + 7][a_sm] = f2tf32(ra1.w);
        if (!TRANSB) {
            float4 c0 = make_float4(f2tf32(rb0.x), f2tf32(rb0.y), f2tf32(rb0.z), f2tf32(rb0.w));
            float4 c1 = make_float4(f2tf32(rb1.x), f2tf32(rb1.y), f2tf32(rb1.z), f2tf32(rb1.w));
            *(float4*)&Bs[buf][b_sk][b_sn]     = c0;
            *(float4*)&Bs[buf][b_sk][b_sn + 4] = c1;
        } else {
            Bs[buf][b_sk + 0][b_sn] = f2tf32(rb0.x);
            Bs[buf][b_sk + 1][b_sn] = f2tf32(rb0.y);
            Bs[buf][b_sk + 2][b_sn] = f2tf32(rb0.z);
            Bs[buf][b_sk + 3][b_sn] = f2tf32(rb0.w);
            Bs[buf][b_sk + 4][b_sn] = f2tf32(rb1.x);
            Bs[buf][b_sk + 5][b_sn] = f2tf32(rb1.y);
            Bs[buf][b_sk + 6][b_sn] = f2tf32(rb1.z);
            Bs[buf][b_sk + 7][b_sn] = f2tf32(rb1.w);
        }
    };

    auto compute = [&](int buf) {
        #pragma unroll
        for (int kb = 0; kb < 16; kb += 8) {
            uint32_t af[4][4], bf[4][2];
            #pragma unroll
            for (int mi = 0; mi < 4; mi++) {
                int mb = wm + mi * 16;
                af[mi][0] = __float_as_uint(As[buf][kb + t4    ][mb + g    ]);
                af[mi][1] = __float_as_uint(As[buf][kb + t4    ][mb + g + 8]);
                af[mi][2] = __float_as_uint(As[buf][kb + t4 + 4][mb + g    ]);
                af[mi][3] = __float_as_uint(As[buf][kb + t4 + 4][mb + g + 8]);
            }
            #pragma unroll
            for (int ni = 0; ni < 4; ni++) {
                int nb = wn + ni * 8;
                bf[ni][0] = __float_as_uint(Bs[buf][kb + t4    ][nb + g]);
                bf[ni][1] = __float_as_uint(Bs[buf][kb + t4 + 4][nb + g]);
            }
            #pragma unroll
            for (int mi = 0; mi < 4; mi++)
                #pragma unroll
                for (int ni = 0; ni < 4; ni++) {
                    asm volatile(
                        "mma.sync.aligned.m16n8k8.row.col.f32.tf32.tf32.f32 "
                        "{%0,%1,%2,%3},{%4,%5,%6,%7},{%8,%9},{%0,%1,%2,%3};"
                        : "+f"(acc[mi][ni][0]), "+f"(acc[mi][ni][1]),
                          "+f"(acc[mi][ni][2]), "+f"(acc[mi][ni][3])
                        : "r"(af[mi][0]), "r"(af[mi][1]),
                          "r"(af[mi][2]), "r"(af[mi][3]),
                          "r"(bf[ni][0]), "r"(bf[ni][1]));
                }
        }
    };

    // ---- pipelined main loop ----
    ldg(0);
    sts(0);
    __syncthreads();
    int cur = 0;
    for (int k0 = 16;; k0 += 16) {
        bool more = k0 < K;
        if (more) ldg(k0);
        compute(cur);
        if (!more) break;
        sts(cur ^ 1);
        __syncthreads();
        cur ^= 1;
    }

    // ---- epilogue ----
    float gate = 1.0f;
    if (gate_logit) gate = 1.0f / (1.0f + expf(-(*gate_logit)));

    #pragma unroll
    for (int mi = 0; mi < 4; mi++) {
        #pragma unroll
        for (int rr = 0; rr < 2; rr++) {
            int m = m0 + wm + mi * 16 + g + rr * 8;
            if (m >= M) continue;
            long long crow = (clen > 0)
                ? (long long)(m / clen) * L_ + cstart + (m % clen)
                : (long long)m;
            float* cp = C + crow * (long long)ldc;
            #pragma unroll
            for (int ni = 0; ni < 4; ni++) {
                int n = n0 + wn + ni * 8 + t4 * 2;
                if (n >= N) continue;
                float v0 = acc[mi][ni][rr * 2 + 0];
                float v1 = acc[mi][ni][rr * 2 + 1];
                if (bias) { v0 += bias[n]; v1 += bias[n + 1]; }
                cp[n]     = v0 * gate;
                cp[n + 1] = v1 * gate;
            }
        }
    }
}

// ---------------------------------------------------------------------------
// Dense GEMM wrapper (NN)
// ---------------------------------------------------------------------------
__global__ __launch_bounds__(256, 2)
void tgemm_nn(const float* __restrict__ A, int lda,
              const float* __restrict__ B, int ldb,
              float* __restrict__ C, int ldc,
              int M, int N, int K,
              const float* __restrict__ bias,
              const float* __restrict__ gate_logit)
{
    gemm_core<0>(A, lda, B, ldb, C, ldc, M, N, K, 0, 0, 0, 0,
                 bias, gate_logit, blockIdx.y * 128, blockIdx.x * 128);
}

// Fused scores kernel: all 10 segments, one launch (2894 tiles)
__global__ __launch_bounds__(256, 2)
void scores_kernel()
{
    int t = blockIdx.x;
    int seg = 0;
    #pragma unroll
    for (int i = 1; i < NSEG; i++) if (t >= c_stp[i]) seg = i;
    int local = t - c_stp[seg];
    int nt = seg + 1;
    int tm = local / nt;
    int tn = local - tm * nt;
    int len = c_len[seg], start = c_start[seg];
    int Nseg = 128 * nt, Mseg = 64 * len;
    gemm_core<1>(g_Q, C_, g_K, C_, g_S + c_base[seg], Nseg,
                 Mseg, Nseg, C_, len, start, 0, 0, nullptr, nullptr,
                 tm * 128, tn * 128);
}

// Fused attn@V kernel: all 10 segments, one launch (2736 tiles)
__global__ __launch_bounds__(256, 2)
void attnv_kernel()
{
    int t = blockIdx.x;
    int seg = 0;
    #pragma unroll
    for (int i = 1; i < NSEG; i++) if (t >= c_atp[i]) seg = i;
    int local = t - c_atp[seg];
    int tm = local >> 3;
    int tn = local & 7;
    int len = c_len[seg], start = c_start[seg];
    int Nseg = 128 * (seg + 1), Mseg = 64 * len;
    gemm_core<0>(g_S + c_base[seg], Nseg, g_V, C_, g_MC, C_,
                 Mseg, C_, Nseg, 0, 0, len, start, nullptr, nullptr,
                 tm * 128, tn * 128);
}

// ---------------------------------------------------------------------------
// Row softmax over segment-packed g_S; scale = (1/32)/clip(exp(log_temp))
// ---------------------------------------------------------------------------
__global__ void softmax_kernel(const float* __restrict__ log_temp)
{
    int row = blockIdx.x;           // b*L + l
    int b = row / L_;
    int l = row - b * L_;

    int seg = 0;
    #pragma unroll
    for (int s2 = 1; s2 < NSEG; s2++)
        if (l >= c_start[s2]) seg = s2;

    const int n   = 128 * (seg + 1);
    const int len = c_len[seg];
    float* p = g_S + c_base[seg] + ((long long)b * len + (l - c_start[seg])) * (long long)n;

    float t = expf(*log_temp);
    t = fminf(fmaxf(t, 0.05f), 1.0f);
    const float scale = (1.0f / 32.0f) / t;

    __shared__ float sh[8];
    const int lane = threadIdx.x & 31;
    const int w    = threadIdx.x >> 5;

    float m = -1e30f;
    for (int j = threadIdx.x; j < n; j += 256) m = fmaxf(m, p[j] * scale);
    #pragma unroll
    for (int o = 16; o; o >>= 1) m = fmaxf(m, __shfl_xor_sync(0xffffffffu, m, o));
    if (lane == 0) sh[w] = m;
    __syncthreads();
    m = sh[lane & 7];
    #pragma unroll
    for (int o = 4; o; o >>= 1) m = fmaxf(m, __shfl_xor_sync(0xffffffffu, m, o));

    float sum = 0.f;
    for (int j = threadIdx.x; j < n; j += 256) {
        float e = expf(p[j] * scale - m);
        p[j] = e;
        sum += e;
    }
    #pragma unroll
    for (int o = 16; o; o >>= 1) sum += __shfl_xor_sync(0xffffffffu, sum, o);
    __syncthreads();
    if (lane == 0) sh[w] = sum;
    __syncthreads();
    sum = sh[lane & 7];
    #pragma unroll
    for (int o = 4; o; o >>= 1) sum += __shfl_xor_sync(0xffffffffu, sum, o);

    const float inv = 1.0f / sum;
    for (int j = threadIdx.x; j < n; j += 256) p[j] *= inv;
}

// Pack wk1|wv1 -> g_w12 [1024x128], bk1|bv1 -> g_b12 [128]
__global__ void pack_w12_kernel(const float* __restrict__ wk1,
                                const float* __restrict__ wv1,
                                const float* __restrict__ bk1,
                                const float* __restrict__ bv1)
{
    int idx = blockIdx.x * 256 + threadIdx.x;
    if (idx < 1024 * 64) {
        int k = idx >> 6, j = idx & 63;
        g_w12[k * 128 + j]      = wk1[idx];
        g_w12[k * 128 + 64 + j] = wv1[idx];
    }
    if (idx < 64) {
        g_b12[idx]      = bk1[idx];
        g_b12[64 + idx] = bv1[idx];
    }
}

__global__ void tail_kernel(float* out, long long off)
{
    if (threadIdx.x < 2) out[off + threadIdx.x] = 0.f;
}

// ---------------------------------------------------------------------------
extern "C" void kernel_launch(void* const* d_in, const int* in_sizes, int n_in,
                              void* d_out, int out_size)
{
    const float* x   = (const float*)d_in[0];
    const float* mem = (const float*)d_in[1];
    const float* Wq  = (const float*)d_in[2];
    const float* Wk  = (const float*)d_in[3];
    const float* Wv  = (const float*)d_in[4];
    const float* wk1 = (const float*)d_in[5];
    const float* bk1 = (const float*)d_in[6];
    const float* wk2 = (const float*)d_in[7];
    const float* bk2 = (const float*)d_in[8];
    const float* wv1 = (const float*)d_in[9];
    const float* bv1 = (const float*)d_in[10];
    const float* wv2 = (const float*)d_in[11];
    const float* bv2 = (const float*)d_in[12];
    const float* gk  = (const float*)d_in[13];
    const float* gv  = (const float*)d_in[14];
    const float* lt  = (const float*)d_in[15];
    float* out = (float*)d_out;

    float *Q, *Kp, *Vp, *MC, *mid, *w12, *b12;
    cudaGetSymbolAddress((void**)&Q,   g_Q);
    cudaGetSymbolAddress((void**)&Kp,  g_K);
    cudaGetSymbolAddress((void**)&Vp,  g_V);
    cudaGetSymbolAddress((void**)&MC,  g_MC);
    cudaGetSymbolAddress((void**)&mid, g_mid);
    cudaGetSymbolAddress((void**)&w12, g_w12);
    cudaGetSymbolAddress((void**)&b12, g_b12);

    // 0) pack bottleneck down-proj weights
    pack_w12_kernel<<<256, 256>>>(wk1, wv1, bk1, bv1);

    // 1) projections
    tgemm_nn<<<dim3(C_ / 128, (B_ * L_) / 128), 256>>>(x,   C_, Wq, C_, Q,  C_,
                                                       B_ * L_,    C_, C_, nullptr, nullptr);
    tgemm_nn<<<dim3(C_ / 128, 10), 256>>>(mem, C_, Wk, C_, Kp, C_,
                                          NSEG * 128, C_, C_, nullptr, nullptr);
    tgemm_nn<<<dim3(C_ / 128, 10), 256>>>(mem, C_, Wv, C_, Vp, C_,
                                          NSEG * 128, C_, C_, nullptr, nullptr);

    // 2) all score GEMMs, one launch
    scores_kernel<<<2894, 256>>>();

    // 3) softmax in-place
    softmax_kernel<<<B_ * L_, 256>>>(lt);

    // 4) all attn @ V GEMMs, one launch
    attnv_kernel<<<2736, 256>>>();

    // 5) fused mid GEMM: mid = MC @ [wk1|wv1] + [bk1|bv1]
    tgemm_nn<<<dim3(1, (B_ * L_) / 128), 256>>>(MC, C_, w12, 128, mid, 128,
                                                B_ * L_, 128, C_, b12, nullptr);

    // 6) up-projections with gate epilogue
    tgemm_nn<<<dim3(C_ / 128, (B_ * L_) / 128), 256>>>(mid,      128, wk2, C_, out, C_,
                                                       B_ * L_, C_, 64, bk2, gk);
    tgemm_nn<<<dim3(C_ / 128, (B_ * L_) / 128), 256>>>(mid + 64, 128, wv2, C_,
                                                       out + (long long)B_ * L_ * C_, C_,
                                                       B_ * L_, C_, 64, bv2, gv);

    // 7) trailing two scalar zeros
    tail_kernel<<<1, 32>>>(out, 2LL * B_ * L_ * C_);
}

// round 6
// speedup vs baseline: 1.3513x; 1.3162x over previous
#include <cuda_runtime.h>
#include <math.h>
#include <stdint.h>

// Problem constants (fixed by setup_inputs)
#define B_   64
#define L_   680
#define C_   1024
#define NSEG 10

__constant__ int       c_start[NSEG] = {0,1,5,14,30,55,91,155,255,424};
__constant__ int       c_len[NSEG]   = {1,4,9,16,25,36,64,100,169,256};
__constant__ long long c_base[NSEG]  = {0LL,8192LL,73728LL,294912LL,819200LL,
                                        1843200LL,3612672LL,7282688LL,13836288LL,26296320LL};
// Tile prefix tables for BM=256, BN=128:
//   mtiles_i = ceil(64*len_i/256) = {1,1,3,4,7,9,16,25,43,64}
//   scores tiles_i = mtiles_i*(i+1); attnv tiles_i = mtiles_i*8
__constant__ int c_stp[NSEG + 1] = {0,1,3,12,28,63,117,229,429,816,1456};
__constant__ int c_atp[NSEG + 1] = {0,8,16,40,72,128,200,328,528,872,1384};

// Static device scratch
__device__ float g_Q  [44564480];   // 43520 x 1024
__device__ float g_K  [1310720];    // 1280 x 1024
__device__ float g_V  [1310720];    // 1280 x 1024
__device__ float g_S  [47267840];   // segment-packed scores/attn
__device__ float g_MC [44564480];   // mem_combined, 43520 x 1024
__device__ float g_mid[5570560];    // 43520 x 128 (mid_k | mid_v)
__device__ float g_w12[131072];     // 1024 x 128 (wk1 | wv1)
__device__ float g_b12[128];        // bk1 | bv1

// Smem geometry: As[2][16][264] (k-major, m up to 256, stride 264 -> mod32=8)
//                Bs[2][16][136] (k-major, n up to 128, stride 136 -> mod32=8)
#define AS_STRIDE 264
#define BS_STRIDE 136
#define SMEM_FLOATS (2*16*AS_STRIDE + 2*16*BS_STRIDE)   // 12800 floats = 51200 B
#define SMEM_BYTES  (SMEM_FLOATS * 4)

__device__ __forceinline__ float f2tf32(float x) {
    uint32_t r;
    asm("cvt.rna.tf32.f32 %0, %1;" : "=r"(r) : "f"(x));
    float out;
    asm("mov.b32 %0, %1;" : "=f"(out) : "r"(r));
    return out;
}

// ---------------------------------------------------------------------------
// TF32 GEMM core: one 256x128 C-tile at (m0, n0), K-loop over full K.
//   A: [M,K] row-major (lda); alen>0 => row remap (m/alen)*680+astart+(m%alen)
//   B: NN = [K,N] (ldb), NT = [N,K] (ldb)
//   C: [M,N] (ldc); clen>0 => row remap
// 256 threads, 8 warps, warp tile 64x64: wm=(w&3)*64, wn=(w>>2)*64.
// Per warp per 16-k tile: 64 LDS + 64 m16n8k8 MMA (1:1), halving smem
// bytes/FLOP vs the 64x32 warp tile.
// ---------------------------------------------------------------------------
template<int TRANSB>
__device__ __forceinline__ void gemm_core(
    const float* __restrict__ A, int lda,
    const float* __restrict__ B, int ldb,
    float* __restrict__ C, int ldc,
    int M, int N, int K,
    int alen, int astart, int clen, int cstart,
    const float* __restrict__ bias,
    const float* __restrict__ gate_logit,
    int m0, int n0)
{
    extern __shared__ float smbuf[];
    float (*As)[16][AS_STRIDE] = (float (*)[16][AS_STRIDE])smbuf;
    float (*Bs)[16][BS_STRIDE] = (float (*)[16][BS_STRIDE])(smbuf + 2 * 16 * AS_STRIDE);

    const int tid  = threadIdx.x;
    const int lane = tid & 31;
    const int w    = tid >> 5;
    const int wm   = (w & 3) * 64;
    const int wn   = (w >> 2) * 64;
    const int g    = lane >> 2;     // 0..7
    const int t4   = lane & 3;      // 0..3

    float acc[4][8][4];
    #pragma unroll
    for (int i = 0; i < 4; i++)
        #pragma unroll
        for (int j = 0; j < 8; j++)
            #pragma unroll
            for (int k = 0; k < 4; k++) acc[i][j][k] = 0.f;

    // ---- A global-load setup: thread loads full 16-k slice of row m0+tid ----
    const int am   = m0 + tid;
    const bool amOK = am < M;
    long long arow = (alen > 0)
        ? (long long)(am / alen) * L_ + astart + (am % alen)
        : (long long)am;
    const float* Aptr = A + arow * (long long)lda;

    // ---- B global-load setup ----
    const float* Bptr;
    bool bOK;
    int b_sk, b_sn;
    if (!TRANSB) {
        int kr = tid >> 4;            // 0..15
        int cn = (tid & 15) * 8;      // 0..120
        bOK  = (n0 + cn) < N;
        Bptr = B + (long long)kr * ldb + n0 + cn;
        b_sk = kr; b_sn = cn;
    } else {
        int bn = tid >> 1;            // 0..127
        int ck = (tid & 1) * 8;
        bOK  = (n0 + bn) < N;
        Bptr = B + (long long)(n0 + bn) * ldb + ck;
        b_sk = ck; b_sn = bn;
    }

    float4 ra0, ra1, ra2, ra3, rb0, rb1;
    const float4 z4 = make_float4(0.f, 0.f, 0.f, 0.f);

    auto ldg = [&](int k0) {
        if (amOK) {
            ra0 = *(const float4*)(Aptr + k0);
            ra1 = *(const float4*)(Aptr + k0 + 4);
            ra2 = *(const float4*)(Aptr + k0 + 8);
            ra3 = *(const float4*)(Aptr + k0 + 12);
        } else { ra0 = z4; ra1 = z4; ra2 = z4; ra3 = z4; }
        if (!TRANSB) {
            const float* p = Bptr + (long long)k0 * ldb;
            if (bOK) { rb0 = *(const float4*)p; rb1 = *(const float4*)(p + 4); }
            else     { rb0 = z4; rb1 = z4; }
        } else {
            if (bOK) { rb0 = *(const float4*)(Bptr + k0); rb1 = *(const float4*)(Bptr + k0 + 4); }
            else     { rb0 = z4; rb1 = z4; }
        }
    };

    auto sts = [&](int buf) {
        {
            float v[16] = {ra0.x, ra0.y, ra0.z, ra0.w, ra1.x, ra1.y, ra1.z, ra1.w,
                           ra2.x, ra2.y, ra2.z, ra2.w, ra3.x, ra3.y, ra3.z, ra3.w};
            #pragma unroll
            for (int j = 0; j < 16; j++)
                As[buf][j][tid] = f2tf32(v[j]);
        }
        if (!TRANSB) {
            float4 c0 = make_float4(f2tf32(rb0.x), f2tf32(rb0.y), f2tf32(rb0.z), f2tf32(rb0.w));
            float4 c1 = make_float4(f2tf32(rb1.x), f2tf32(rb1.y), f2tf32(rb1.z), f2tf32(rb1.w));
            *(float4*)&Bs[buf][b_sk][b_sn]     = c0;
            *(float4*)&Bs[buf][b_sk][b_sn + 4] = c1;
        } else {
            Bs[buf][b_sk + 0][b_sn] = f2tf32(rb0.x);
            Bs[buf][b_sk + 1][b_sn] = f2tf32(rb0.y);
            Bs[buf][b_sk + 2][b_sn] = f2tf32(rb0.z);
            Bs[buf][b_sk + 3][b_sn] = f2tf32(rb0.w);
            Bs[buf][b_sk + 4][b_sn] = f2tf32(rb1.x);
            Bs[buf][b_sk + 5][b_sn] = f2tf32(rb1.y);
            Bs[buf][b_sk + 6][b_sn] = f2tf32(rb1.z);
            Bs[buf][b_sk + 7][b_sn] = f2tf32(rb1.w);
        }
    };

    auto compute = [&](int buf) {
        #pragma unroll
        for (int kb = 0; kb < 16; kb += 8) {
            uint32_t af[4][4], bf[8][2];
            #pragma unroll
            for (int mi = 0; mi < 4; mi++) {
                int mb = wm + mi * 16;
                af[mi][0] = __float_as_uint(As[buf][kb + t4    ][mb + g    ]);
                af[mi][1] = __float_as_uint(As[buf][kb + t4    ][mb + g + 8]);
                af[mi][2] = __float_as_uint(As[buf][kb + t4 + 4][mb + g    ]);
                af[mi][3] = __float_as_uint(As[buf][kb + t4 + 4][mb + g + 8]);
            }
            #pragma unroll
            for (int ni = 0; ni < 8; ni++) {
                int nb = wn + ni * 8;
                bf[ni][0] = __float_as_uint(Bs[buf][kb + t4    ][nb + g]);
                bf[ni][1] = __float_as_uint(Bs[buf][kb + t4 + 4][nb + g]);
            }
            #pragma unroll
            for (int mi = 0; mi < 4; mi++)
                #pragma unroll
                for (int ni = 0; ni < 8; ni++) {
                    asm volatile(
                        "mma.sync.aligned.m16n8k8.row.col.f32.tf32.tf32.f32 "
                        "{%0,%1,%2,%3},{%4,%5,%6,%7},{%8,%9},{%0,%1,%2,%3};"
                        : "+f"(acc[mi][ni][0]), "+f"(acc[mi][ni][1]),
                          "+f"(acc[mi][ni][2]), "+f"(acc[mi][ni][3])
                        : "r"(af[mi][0]), "r"(af[mi][1]),
                          "r"(af[mi][2]), "r"(af[mi][3]),
                          "r"(bf[ni][0]), "r"(bf[ni][1]));
                }
        }
    };

    // ---- pipelined main loop ----
    ldg(0);
    sts(0);
    __syncthreads();
    int cur = 0;
    for (int k0 = 16;; k0 += 16) {
        bool more = k0 < K;
        if (more) ldg(k0);
        compute(cur);
        if (!more) break;
        sts(cur ^ 1);
        __syncthreads();
        cur ^= 1;
    }

    // ---- epilogue ----
    float gate = 1.0f;
    if (gate_logit) gate = 1.0f / (1.0f + expf(-(*gate_logit)));

    #pragma unroll
    for (int mi = 0; mi < 4; mi++) {
        #pragma unroll
        for (int rr = 0; rr < 2; rr++) {
            int m = m0 + wm + mi * 16 + g + rr * 8;
            if (m >= M) continue;
            long long crow = (clen > 0)
                ? (long long)(m / clen) * L_ + cstart + (m % clen)
                : (long long)m;
            float* cp = C + crow * (long long)ldc;
            #pragma unroll
            for (int ni = 0; ni < 8; ni++) {
                int n = n0 + wn + ni * 8 + t4 * 2;
                if (n >= N) continue;
                float v0 = acc[mi][ni][rr * 2 + 0];
                float v1 = acc[mi][ni][rr * 2 + 1];
                if (bias) { v0 += bias[n]; v1 += bias[n + 1]; }
                cp[n]     = v0 * gate;
                cp[n + 1] = v1 * gate;
            }
        }
    }
}

// ---------------------------------------------------------------------------
// Dense GEMM wrapper (NN)
// ---------------------------------------------------------------------------
__global__ void tgemm_nn(const float* __restrict__ A, int lda,
                         const float* __restrict__ B, int ldb,
                         float* __restrict__ C, int ldc,
                         int M, int N, int K,
                         const float* __restrict__ bias,
                         const float* __restrict__ gate_logit)
{
    gemm_core<0>(A, lda, B, ldb, C, ldc, M, N, K, 0, 0, 0, 0,
                 bias, gate_logit, blockIdx.y * 256, blockIdx.x * 128);
}

// Fused scores kernel: all 10 segments, one launch (1456 tiles)
__global__ void scores_kernel()
{
    int t = blockIdx.x;
    int seg = 0;
    #pragma unroll
    for (int i = 1; i < NSEG; i++) if (t >= c_stp[i]) seg = i;
    int local = t - c_stp[seg];
    int nt = seg + 1;
    int tm = local / nt;
    int tn = local - tm * nt;
    int len = c_len[seg], start = c_start[seg];
    int Nseg = 128 * nt, Mseg = 64 * len;
    gemm_core<1>(g_Q, C_, g_K, C_, g_S + c_base[seg], Nseg,
                 Mseg, Nseg, C_, len, start, 0, 0, nullptr, nullptr,
                 tm * 256, tn * 128);
}

// Fused attn@V kernel: all 10 segments, one launch (1384 tiles)
__global__ void attnv_kernel()
{
    int t = blockIdx.x;
    int seg = 0;
    #pragma unroll
    for (int i = 1; i < NSEG; i++) if (t >= c_atp[i]) seg = i;
    int local = t - c_atp[seg];
    int tm = local >> 3;
    int tn = local & 7;
    int len = c_len[seg], start = c_start[seg];
    int Nseg = 128 * (seg + 1), Mseg = 64 * len;
    gemm_core<0>(g_S + c_base[seg], Nseg, g_V, C_, g_MC, C_,
                 Mseg, C_, Nseg, 0, 0, len, start, nullptr, nullptr,
                 tm * 256, tn * 128);
}

// ---------------------------------------------------------------------------
// Row softmax over segment-packed g_S; scale = (1/32)/clip(exp(log_temp))
// ---------------------------------------------------------------------------
__global__ void softmax_kernel(const float* __restrict__ log_temp)
{
    int row = blockIdx.x;           // b*L + l
    int b = row / L_;
    int l = row - b * L_;

    int seg = 0;
    #pragma unroll
    for (int s2 = 1; s2 < NSEG; s2++)
        if (l >= c_start[s2]) seg = s2;

    const int n   = 128 * (seg + 1);
    const int len = c_len[seg];
    float* p = g_S + c_base[seg] + ((long long)b * len + (l - c_start[seg])) * (long long)n;

    float t = expf(*log_temp);
    t = fminf(fmaxf(t, 0.05f), 1.0f);
    const float scale = (1.0f / 32.0f) / t;

    __shared__ float sh[8];
    const int lane = threadIdx.x & 31;
    const int w    = threadIdx.x >> 5;

    float m = -1e30f;
    for (int j = threadIdx.x; j < n; j += 256) m = fmaxf(m, p[j] * scale);
    #pragma unroll
    for (int o = 16; o; o >>= 1) m = fmaxf(m, __shfl_xor_sync(0xffffffffu, m, o));
    if (lane == 0) sh[w] = m;
    __syncthreads();
    m = sh[lane & 7];
    #pragma unroll
    for (int o = 4; o; o >>= 1) m = fmaxf(m, __shfl_xor_sync(0xffffffffu, m, o));

    float sum = 0.f;
    for (int j = threadIdx.x; j < n; j += 256) {
        float e = expf(p[j] * scale - m);
        p[j] = e;
        sum += e;
    }
    #pragma unroll
    for (int o = 16; o; o >>= 1) sum += __shfl_xor_sync(0xffffffffu, sum, o);
    __syncthreads();
    if (lane == 0) sh[w] = sum;
    __syncthreads();
    sum = sh[lane & 7];
    #pragma unroll
    for (int o = 4; o; o >>= 1) sum += __shfl_xor_sync(0xffffffffu, sum, o);

    const float inv = 1.0f / sum;
    for (int j = threadIdx.x; j < n; j += 256) p[j] *= inv;
}

// Pack wk1|wv1 -> g_w12 [1024x128], bk1|bv1 -> g_b12 [128]
__global__ void pack_w12_kernel(const float* __restrict__ wk1,
                                const float* __restrict__ wv1,
                                const float* __restrict__ bk1,
                                const float* __restrict__ bv1)
{
    int idx = blockIdx.x * 256 + threadIdx.x;
    if (idx < 1024 * 64) {
        int k = idx >> 6, j = idx & 63;
        g_w12[k * 128 + j]      = wk1[idx];
        g_w12[k * 128 + 64 + j] = wv1[idx];
    }
    if (idx < 64) {
        g_b12[idx]      = bk1[idx];
        g_b12[64 + idx] = bv1[idx];
    }
}

__global__ void tail_kernel(float* out, long long off)
{
    if (threadIdx.x < 2) out[off + threadIdx.x] = 0.f;
}

// ---------------------------------------------------------------------------
extern "C" void kernel_launch(void* const* d_in, const int* in_sizes, int n_in,
                              void* d_out, int out_size)
{
    const float* x   = (const float*)d_in[0];
    const float* mem = (const float*)d_in[1];
    const float* Wq  = (const float*)d_in[2];
    const float* Wk  = (const float*)d_in[3];
    const float* Wv  = (const float*)d_in[4];
    const float* wk1 = (const float*)d_in[5];
    const float* bk1 = (const float*)d_in[6];
    const float* wk2 = (const float*)d_in[7];
    const float* bk2 = (const float*)d_in[8];
    const float* wv1 = (const float*)d_in[9];
    const float* bv1 = (const float*)d_in[10];
    const float* wv2 = (const float*)d_in[11];
    const float* bv2 = (const float*)d_in[12];
    const float* gk  = (const float*)d_in[13];
    const float* gv  = (const float*)d_in[14];
    const float* lt  = (const float*)d_in[15];
    float* out = (float*)d_out;

    float *Q, *Kp, *Vp, *MC, *mid, *w12, *b12;
    cudaGetSymbolAddress((void**)&Q,   g_Q);
    cudaGetSymbolAddress((void**)&Kp,  g_K);
    cudaGetSymbolAddress((void**)&Vp,  g_V);
    cudaGetSymbolAddress((void**)&MC,  g_MC);
    cudaGetSymbolAddress((void**)&mid, g_mid);
    cudaGetSymbolAddress((void**)&w12, g_w12);
    cudaGetSymbolAddress((void**)&b12, g_b12);

    // Opt into >48KB dynamic smem (idempotent; host-side, capture-safe)
    cudaFuncSetAttribute(tgemm_nn,      cudaFuncAttributeMaxDynamicSharedMemorySize, SMEM_BYTES);
    cudaFuncSetAttribute(scores_kernel, cudaFuncAttributeMaxDynamicSharedMemorySize, SMEM_BYTES);
    cudaFuncSetAttribute(attnv_kernel,  cudaFuncAttributeMaxDynamicSharedMemorySize, SMEM_BYTES);

    // 0) pack bottleneck down-proj weights
    pack_w12_kernel<<<256, 256>>>(wk1, wv1, bk1, bv1);

    // 1) projections   (BM=256, BN=128)
    tgemm_nn<<<dim3(C_ / 128, (B_ * L_) / 256), 256, SMEM_BYTES>>>(
        x,   C_, Wq, C_, Q,  C_, B_ * L_,    C_, C_, nullptr, nullptr);
    tgemm_nn<<<dim3(C_ / 128, 5), 256, SMEM_BYTES>>>(
        mem, C_, Wk, C_, Kp, C_, NSEG * 128, C_, C_, nullptr, nullptr);
    tgemm_nn<<<dim3(C_ / 128, 5), 256, SMEM_BYTES>>>(
        mem, C_, Wv, C_, Vp, C_, NSEG * 128, C_, C_, nullptr, nullptr);

    // 2) all score GEMMs, one launch
    scores_kernel<<<1456, 256, SMEM_BYTES>>>();

    // 3) softmax in-place
    softmax_kernel<<<B_ * L_, 256>>>(lt);

    // 4) all attn @ V GEMMs, one launch
    attnv_kernel<<<1384, 256, SMEM_BYTES>>>();

    // 5) fused mid GEMM: mid = MC @ [wk1|wv1] + [bk1|bv1]   (43520 x 128, K=1024)
    tgemm_nn<<<dim3(1, (B_ * L_) / 256), 256, SMEM_BYTES>>>(
        MC, C_, w12, 128, mid, 128, B_ * L_, 128, C_, b12, nullptr);

    // 6) up-projections with gate epilogue (K=64, A lda=128)
    tgemm_nn<<<dim3(C_ / 128, (B_ * L_) / 256), 256, SMEM_BYTES>>>(
        mid,      128, wk2, C_, out, C_, B_ * L_, C_, 64, bk2, gk);
    tgemm_nn<<<dim3(C_ / 128, (B_ * L_) / 256), 256, SMEM_BYTES>>>(
        mid + 64, 128, wv2, C_, out + (long long)B_ * L_ * C_, C_,
        B_ * L_, C_, 64, bv2, gv);

    // 7) trailing two scalar zeros
    tail_kernel<<<1, 32>>>(out, 2LL * B_ * L_ * C_);
}